// round 1
// baseline (speedup 1.0000x reference)
#include <cuda_runtime.h>
#include <math.h>

#define B_ 8
#define C_ 256
#define N_ 4096
#define O_ 128

// Scratch (allocation-free rule: __device__ globals). 4 x 16MB = 64MB.
__device__ float d_theta[(size_t)B_ * N_ * O_];
__device__ float d_phi[(size_t)B_ * N_ * O_];
__device__ float d_gv[(size_t)B_ * N_ * O_];
__device__ float d_y[(size_t)B_ * N_ * O_];

// ---------------------------------------------------------------------------
// Kernel 1: channel projections.  out[b][n][o] = sum_c W[o][c]*x[b][c][n] + bias[o]
// grid (32 n-tiles, 8 batch, 3 projections), 256 threads, 128x128 tile, K=256.
// ---------------------------------------------------------------------------
__global__ __launch_bounds__(256) void proj_kernel(
    const float* __restrict__ x,
    const float* __restrict__ wt, const float* __restrict__ bt,
    const float* __restrict__ wp, const float* __restrict__ bp,
    const float* __restrict__ wg, const float* __restrict__ bg)
{
    __shared__ float xs[32][132];   // xs[c_local][n]
    __shared__ float ws[32][132];   // ws[c_local][o]  (W transposed)

    const int b  = blockIdx.y;
    const int n0 = blockIdx.x * 128;
    const float* W; const float* bias; float* out;
    if (blockIdx.z == 0)      { W = wt; bias = bt; out = d_theta; }
    else if (blockIdx.z == 1) { W = wp; bias = bp; out = d_phi;   }
    else                      { W = wg; bias = bg; out = d_gv;    }

    const int tid = threadIdx.x;
    const int tx = tid & 15;   // o direction
    const int ty = tid >> 4;   // n direction

    float acc[8][8];
#pragma unroll
    for (int i = 0; i < 8; i++)
#pragma unroll
        for (int j = 0; j < 8; j++) acc[i][j] = 0.f;

    for (int c0 = 0; c0 < C_; c0 += 32) {
        __syncthreads();
        // x chunk: [32 c][128 n], coalesced, float4 smem writes
#pragma unroll
        for (int r = 0; r < 4; r++) {
            int idx = tid + r * 256;           // 1024 float4s
            int cc = idx >> 5;
            int nv = (idx & 31) << 2;
            float4 v = *(const float4*)(x + ((size_t)(b * C_ + c0 + cc)) * N_ + n0 + nv);
            *(float4*)&xs[cc][nv] = v;
        }
        // W chunk: read W[o][c] coalesced along c, store transposed ws[c][o]
#pragma unroll
        for (int r = 0; r < 4; r++) {
            int idx = tid + r * 256;
            int o  = idx >> 3;
            int cv = (idx & 7) << 2;
            float4 w = *(const float4*)(W + (size_t)o * C_ + c0 + cv);
            ws[cv + 0][o] = w.x;
            ws[cv + 1][o] = w.y;
            ws[cv + 2][o] = w.z;
            ws[cv + 3][o] = w.w;
        }
        __syncthreads();
#pragma unroll
        for (int cc = 0; cc < 32; cc++) {
            float a[8];
#pragma unroll
            for (int i = 0; i < 8; i++) a[i] = xs[cc][ty * 8 + i];
            float4 u = *(const float4*)&ws[cc][tx * 8];
            float4 v = *(const float4*)&ws[cc][tx * 8 + 4];
            float bb[8] = {u.x, u.y, u.z, u.w, v.x, v.y, v.z, v.w};
#pragma unroll
            for (int i = 0; i < 8; i++)
#pragma unroll
                for (int j = 0; j < 8; j++) acc[i][j] += a[i] * bb[j];
        }
    }

    float4 bu = *(const float4*)(bias + tx * 8);
    float4 bv = *(const float4*)(bias + tx * 8 + 4);
    float bb[8] = {bu.x, bu.y, bu.z, bu.w, bv.x, bv.y, bv.z, bv.w};
#pragma unroll
    for (int i = 0; i < 8; i++) {
        float* row = out + ((size_t)b * N_ + n0 + ty * 8 + i) * O_ + tx * 8;
        float4 o0 = make_float4(acc[i][0] + bb[0], acc[i][1] + bb[1],
                                acc[i][2] + bb[2], acc[i][3] + bb[3]);
        float4 o1 = make_float4(acc[i][4] + bb[4], acc[i][5] + bb[5],
                                acc[i][6] + bb[6], acc[i][7] + bb[7]);
        *(float4*)row = o0;
        *(float4*)(row + 4) = o1;
    }
}

// ---------------------------------------------------------------------------
// Kernel 2: flash attention.  y[b][n][o] = softmax(theta phi)(g)
// grid (32 q-tiles, 8 batch), 256 threads. Tiles: Q 128x128, K/V 128x128.
// smem: Qs[128][129] (transposed), KP union (Ks[128][132] / Pt[128][129]),
//       Vs[128][132]  -> 201216 B dynamic.
// ---------------------------------------------------------------------------
#define ATTN_SMEM ((128 * 129 + 128 * 132 + 128 * 132) * 4)

__global__ __launch_bounds__(256, 1) void attn_kernel()
{
    extern __shared__ float sm[];
    float* Qs = sm;                 // [o][q], pad 129
    float* KP = sm + 128 * 129;     // Ks: [o][k] pad 132  /  Pt: [k][q] pad 129
    float* Vs = KP + 128 * 132;     // [k][o], pad 132

    const int b  = blockIdx.y;
    const int q0 = blockIdx.x * 128;
    const float* Q = d_theta + (size_t)b * N_ * O_;
    const float* K = d_phi   + (size_t)b * N_ * O_;
    const float* V = d_gv    + (size_t)b * N_ * O_;

    const int tid = threadIdx.x;
    const int tx = tid & 15;   // k / o direction
    const int ty = tid >> 4;   // q direction

    // Load Q tile transposed: Qs[o][q]
#pragma unroll
    for (int r = 0; r < 16; r++) {
        int idx = tid + r * 256;
        int q  = idx >> 5;
        int kv = (idx & 31) << 2;
        float4 v = *(const float4*)(Q + (size_t)(q0 + q) * O_ + kv);
        Qs[(kv + 0) * 129 + q] = v.x;
        Qs[(kv + 1) * 129 + q] = v.y;
        Qs[(kv + 2) * 129 + q] = v.z;
        Qs[(kv + 3) * 129 + q] = v.w;
    }

    float acc[8][8];
    float p[8][8];
    float m[8], l[8];
#pragma unroll
    for (int i = 0; i < 8; i++) {
        m[i] = -1e30f;
        l[i] = 0.f;
#pragma unroll
        for (int j = 0; j < 8; j++) acc[i][j] = 0.f;
    }

    for (int jt = 0; jt < 32; jt++) {
        const int k0 = jt * 128;
        __syncthreads();   // previous PV done (also covers Q-load on first iter)

        // K tile transposed: Ks[o][k].  Lanes along k -> conflict-free STS,
        // strided LDG (L1 absorbs it).
#pragma unroll
        for (int r = 0; r < 16; r++) {
            int idx = tid + r * 256;
            int kq  = idx & 31;
            int grp = idx >> 5;
            int kv  = (grp & 31) << 2;
            int kb  = grp >> 5;
            int k   = kb * 32 + kq;
            float4 v = *(const float4*)(K + (size_t)(k0 + k) * O_ + kv);
            KP[(kv + 0) * 132 + k] = v.x;
            KP[(kv + 1) * 132 + k] = v.y;
            KP[(kv + 2) * 132 + k] = v.z;
            KP[(kv + 3) * 132 + k] = v.w;
        }
        // V tile natural: Vs[k][o], fully coalesced both sides
#pragma unroll
        for (int r = 0; r < 16; r++) {
            int idx = tid + r * 256;
            int k  = idx >> 5;
            int ov = (idx & 31) << 2;
            float4 v = *(const float4*)(V + (size_t)(k0 + k) * O_ + ov);
            *(float4*)&Vs[k * 132 + ov] = v;
        }
        __syncthreads();

        // S = Q K^T  (p holds logits)
#pragma unroll
        for (int i = 0; i < 8; i++)
#pragma unroll
            for (int j = 0; j < 8; j++) p[i][j] = 0.f;
#pragma unroll 4
        for (int kk = 0; kk < 128; kk++) {
            float a[8];
#pragma unroll
            for (int i = 0; i < 8; i++) a[i] = Qs[kk * 129 + ty * 8 + i];
            float4 u = *(const float4*)&KP[kk * 132 + tx * 8];
            float4 v = *(const float4*)&KP[kk * 132 + tx * 8 + 4];
            float bb[8] = {u.x, u.y, u.z, u.w, v.x, v.y, v.z, v.w};
#pragma unroll
            for (int i = 0; i < 8; i++)
#pragma unroll
                for (int j = 0; j < 8; j++) p[i][j] += a[i] * bb[j];
        }

        // Online softmax update (row stats shared across the 16 tx lanes)
#pragma unroll
        for (int i = 0; i < 8; i++) {
            float rm = p[i][0];
#pragma unroll
            for (int j = 1; j < 8; j++) rm = fmaxf(rm, p[i][j]);
            rm = fmaxf(rm, __shfl_xor_sync(0xffffffffu, rm, 8));
            rm = fmaxf(rm, __shfl_xor_sync(0xffffffffu, rm, 4));
            rm = fmaxf(rm, __shfl_xor_sync(0xffffffffu, rm, 2));
            rm = fmaxf(rm, __shfl_xor_sync(0xffffffffu, rm, 1));
            float mn = fmaxf(m[i], rm);
            float sc = __expf(m[i] - mn);
            m[i] = mn;
            float rs = 0.f;
#pragma unroll
            for (int j = 0; j < 8; j++) {
                p[i][j] = __expf(p[i][j] - mn);
                rs += p[i][j];
            }
            rs += __shfl_xor_sync(0xffffffffu, rs, 8);
            rs += __shfl_xor_sync(0xffffffffu, rs, 4);
            rs += __shfl_xor_sync(0xffffffffu, rs, 2);
            rs += __shfl_xor_sync(0xffffffffu, rs, 1);
            l[i] = l[i] * sc + rs;
#pragma unroll
            for (int j = 0; j < 8; j++) acc[i][j] *= sc;
        }

        __syncthreads();   // all lanes done reading Ks
        // Write P transposed: Pt[k][q] (reuses Ks region)
#pragma unroll
        for (int i = 0; i < 8; i++)
#pragma unroll
            for (int j = 0; j < 8; j++)
                KP[(tx * 8 + j) * 129 + ty * 8 + i] = p[i][j];
        __syncthreads();

        // acc += P V
#pragma unroll 4
        for (int kk = 0; kk < 128; kk++) {
            float a[8];
#pragma unroll
            for (int i = 0; i < 8; i++) a[i] = KP[kk * 129 + ty * 8 + i];
            float4 u = *(const float4*)&Vs[kk * 132 + tx * 8];
            float4 v = *(const float4*)&Vs[kk * 132 + tx * 8 + 4];
            float bb[8] = {u.x, u.y, u.z, u.w, v.x, v.y, v.z, v.w};
#pragma unroll
            for (int i = 0; i < 8; i++)
#pragma unroll
                for (int j = 0; j < 8; j++) acc[i][j] += a[i] * bb[j];
        }
    }

    float* Y = d_y + (size_t)b * N_ * O_;
#pragma unroll
    for (int i = 0; i < 8; i++) {
        float inv = 1.f / l[i];
        float* row = Y + (size_t)(q0 + ty * 8 + i) * O_ + tx * 8;
        float4 o0 = make_float4(acc[i][0] * inv, acc[i][1] * inv,
                                acc[i][2] * inv, acc[i][3] * inv);
        float4 o1 = make_float4(acc[i][4] * inv, acc[i][5] * inv,
                                acc[i][6] * inv, acc[i][7] * inv);
        *(float4*)row = o0;
        *(float4*)(row + 4) = o1;
    }
}

// ---------------------------------------------------------------------------
// Kernel 3: out = x + BN(W_out y + b_out).  grid (32 n-tiles, 2 c-tiles, 8 b).
// Tile 128c x 128n, K = O = 128 (single chunk).
// ---------------------------------------------------------------------------
#define OUT_SMEM (2 * 128 * 132 * 4)

__global__ __launch_bounds__(256, 1) void out_kernel(
    const float* __restrict__ x,
    const float* __restrict__ wo, const float* __restrict__ bo,
    const float* __restrict__ gamma, const float* __restrict__ beta,
    const float* __restrict__ mean, const float* __restrict__ var,
    float* __restrict__ out)
{
    extern __shared__ float sm[];
    float* ws2 = sm;              // [o][c], pad 132
    float* ys  = sm + 128 * 132;  // [o][n], pad 132

    const int b  = blockIdx.z;
    const int c0 = blockIdx.y * 128;
    const int n0 = blockIdx.x * 128;
    const int tid = threadIdx.x;
    const int tx = tid & 15;   // n direction
    const int ty = tid >> 4;   // c direction

    // w_out[c][o] -> ws2[o][c]  (lanes along c: conflict-free STS)
#pragma unroll
    for (int r = 0; r < 16; r++) {
        int idx = tid + r * 256;
        int cq  = idx & 31;
        int grp = idx >> 5;
        int ov  = (grp & 31) << 2;
        int cb  = grp >> 5;
        int c   = cb * 32 + cq;
        float4 v = *(const float4*)(wo + (size_t)(c0 + c) * O_ + ov);
        ws2[(ov + 0) * 132 + c] = v.x;
        ws2[(ov + 1) * 132 + c] = v.y;
        ws2[(ov + 2) * 132 + c] = v.z;
        ws2[(ov + 3) * 132 + c] = v.w;
    }
    // y[n][o] -> ys[o][n]  (lanes along n)
#pragma unroll
    for (int r = 0; r < 16; r++) {
        int idx = tid + r * 256;
        int nq  = idx & 31;
        int grp = idx >> 5;
        int ov  = (grp & 31) << 2;
        int nb  = grp >> 5;
        int n   = nb * 32 + nq;
        float4 v = *(const float4*)(d_y + ((size_t)b * N_ + n0 + n) * O_ + ov);
        ys[(ov + 0) * 132 + n] = v.x;
        ys[(ov + 1) * 132 + n] = v.y;
        ys[(ov + 2) * 132 + n] = v.z;
        ys[(ov + 3) * 132 + n] = v.w;
    }
    __syncthreads();

    float acc[8][8];
#pragma unroll
    for (int i = 0; i < 8; i++)
#pragma unroll
        for (int j = 0; j < 8; j++) acc[i][j] = 0.f;

#pragma unroll 4
    for (int o = 0; o < 128; o++) {
        float a[8];
#pragma unroll
        for (int i = 0; i < 8; i++) a[i] = ws2[o * 132 + ty * 8 + i];
        float4 u = *(const float4*)&ys[o * 132 + tx * 8];
        float4 v = *(const float4*)&ys[o * 132 + tx * 8 + 4];
        float bb[8] = {u.x, u.y, u.z, u.w, v.x, v.y, v.z, v.w};
#pragma unroll
        for (int i = 0; i < 8; i++)
#pragma unroll
            for (int j = 0; j < 8; j++) acc[i][j] += a[i] * bb[j];
    }

    // Epilogue: BN (eval) + residual
#pragma unroll
    for (int i = 0; i < 8; i++) {
        int c = c0 + ty * 8 + i;
        float inv = gamma[c] * rsqrtf(var[c] + 1e-5f);
        float sh  = beta[c] - mean[c] * inv + bo[c] * inv;
        const float* xr = x   + ((size_t)(b * C_ + c)) * N_ + n0 + tx * 8;
        float*       orow = out + ((size_t)(b * C_ + c)) * N_ + n0 + tx * 8;
        float4 x0 = *(const float4*)xr;
        float4 x1 = *(const float4*)(xr + 4);
        float4 o0 = make_float4(x0.x + acc[i][0] * inv + sh,
                                x0.y + acc[i][1] * inv + sh,
                                x0.z + acc[i][2] * inv + sh,
                                x0.w + acc[i][3] * inv + sh);
        float4 o1 = make_float4(x1.x + acc[i][4] * inv + sh,
                                x1.y + acc[i][5] * inv + sh,
                                x1.z + acc[i][6] * inv + sh,
                                x1.w + acc[i][7] * inv + sh);
        *(float4*)orow       = o0;
        *(float4*)(orow + 4) = o1;
    }
}

// ---------------------------------------------------------------------------
extern "C" void kernel_launch(void* const* d_in, const int* in_sizes, int n_in,
                              void* d_out, int out_size)
{
    const float* x     = (const float*)d_in[0];
    const float* wt    = (const float*)d_in[1];
    const float* bt    = (const float*)d_in[2];
    const float* wp    = (const float*)d_in[3];
    const float* bp    = (const float*)d_in[4];
    const float* wg    = (const float*)d_in[5];
    const float* bg    = (const float*)d_in[6];
    const float* wo    = (const float*)d_in[7];
    const float* bo    = (const float*)d_in[8];
    const float* gamma = (const float*)d_in[9];
    const float* beta  = (const float*)d_in[10];
    const float* mean  = (const float*)d_in[11];
    const float* var   = (const float*)d_in[12];
    float* out = (float*)d_out;

    cudaFuncSetAttribute(attn_kernel, cudaFuncAttributeMaxDynamicSharedMemorySize, ATTN_SMEM);
    cudaFuncSetAttribute(out_kernel,  cudaFuncAttributeMaxDynamicSharedMemorySize, OUT_SMEM);

    proj_kernel<<<dim3(32, 8, 3), 256>>>(x, wt, bt, wp, bp, wg, bg);
    attn_kernel<<<dim3(32, 8), 256, ATTN_SMEM>>>();
    out_kernel<<<dim3(32, 2, 8), 256, OUT_SMEM>>>(x, wo, bo, gamma, beta, mean, var, out);
}

// round 2
// speedup vs baseline: 1.0016x; 1.0016x over previous
#include <cuda_runtime.h>
#include <math.h>

#define B_ 8
#define C_ 256
#define N_ 4096
#define O_ 128

// Scratch (allocation-free rule: __device__ globals). 4 x 16MB = 64MB.
__device__ float d_theta[(size_t)B_ * N_ * O_];
__device__ float d_phi[(size_t)B_ * N_ * O_];
__device__ float d_gv[(size_t)B_ * N_ * O_];
__device__ float d_y[(size_t)B_ * N_ * O_];

// ---------------------------------------------------------------------------
// Kernel 1: channel projections.  out[b][n][o] = sum_c W[o][c]*x[b][c][n] + bias[o]
// grid (32 n-tiles, 8 batch, 3 projections), 256 threads, 128x128 tile, K=256.
// ---------------------------------------------------------------------------
__global__ __launch_bounds__(256) void proj_kernel(
    const float* __restrict__ x,
    const float* __restrict__ wt, const float* __restrict__ bt,
    const float* __restrict__ wp, const float* __restrict__ bp,
    const float* __restrict__ wg, const float* __restrict__ bg)
{
    __shared__ float xs[32][132];   // xs[c_local][n]
    __shared__ float ws[32][132];   // ws[c_local][o]  (W transposed)

    const int b  = blockIdx.y;
    const int n0 = blockIdx.x * 128;
    const float* W; const float* bias; float* out;
    if (blockIdx.z == 0)      { W = wt; bias = bt; out = d_theta; }
    else if (blockIdx.z == 1) { W = wp; bias = bp; out = d_phi;   }
    else                      { W = wg; bias = bg; out = d_gv;    }

    const int tid = threadIdx.x;
    const int tx = tid & 15;   // o direction
    const int ty = tid >> 4;   // n direction

    float acc[8][8];
#pragma unroll
    for (int i = 0; i < 8; i++)
#pragma unroll
        for (int j = 0; j < 8; j++) acc[i][j] = 0.f;

    for (int c0 = 0; c0 < C_; c0 += 32) {
        __syncthreads();
        // x chunk: [32 c][128 n], coalesced, float4 smem writes
#pragma unroll
        for (int r = 0; r < 4; r++) {
            int idx = tid + r * 256;           // 1024 float4s
            int cc = idx >> 5;
            int nv = (idx & 31) << 2;
            float4 v = *(const float4*)(x + ((size_t)(b * C_ + c0 + cc)) * N_ + n0 + nv);
            *(float4*)&xs[cc][nv] = v;
        }
        // W chunk: read W[o][c] coalesced along c, store transposed ws[c][o]
#pragma unroll
        for (int r = 0; r < 4; r++) {
            int idx = tid + r * 256;
            int o  = idx >> 3;
            int cv = (idx & 7) << 2;
            float4 w = *(const float4*)(W + (size_t)o * C_ + c0 + cv);
            ws[cv + 0][o] = w.x;
            ws[cv + 1][o] = w.y;
            ws[cv + 2][o] = w.z;
            ws[cv + 3][o] = w.w;
        }
        __syncthreads();
#pragma unroll
        for (int cc = 0; cc < 32; cc++) {
            float a[8];
#pragma unroll
            for (int i = 0; i < 8; i++) a[i] = xs[cc][ty * 8 + i];
            float4 u = *(const float4*)&ws[cc][tx * 8];
            float4 v = *(const float4*)&ws[cc][tx * 8 + 4];
            float bb[8] = {u.x, u.y, u.z, u.w, v.x, v.y, v.z, v.w};
#pragma unroll
            for (int i = 0; i < 8; i++)
#pragma unroll
                for (int j = 0; j < 8; j++) acc[i][j] += a[i] * bb[j];
        }
    }

    float4 bu = *(const float4*)(bias + tx * 8);
    float4 bv = *(const float4*)(bias + tx * 8 + 4);
    float bb[8] = {bu.x, bu.y, bu.z, bu.w, bv.x, bv.y, bv.z, bv.w};
#pragma unroll
    for (int i = 0; i < 8; i++) {
        float* row = out + ((size_t)b * N_ + n0 + ty * 8 + i) * O_ + tx * 8;
        float4 o0 = make_float4(acc[i][0] + bb[0], acc[i][1] + bb[1],
                                acc[i][2] + bb[2], acc[i][3] + bb[3]);
        float4 o1 = make_float4(acc[i][4] + bb[4], acc[i][5] + bb[5],
                                acc[i][6] + bb[6], acc[i][7] + bb[7]);
        *(float4*)row = o0;
        *(float4*)(row + 4) = o1;
    }
}

// ---------------------------------------------------------------------------
// Kernel 2: flash attention.  y[b][n][o] = softmax(theta phi)(g)
// grid (32 q-tiles, 8 batch), 256 threads. Tiles: Q 128x128, K/V 128x128.
// smem: Qs[128][129] (transposed), KP union (Ks[128][132] / Pt[128][129]),
//       Vs[128][132]  -> 201216 B dynamic.
// ---------------------------------------------------------------------------
#define ATTN_SMEM ((128 * 129 + 128 * 132 + 128 * 132) * 4)

__global__ __launch_bounds__(256, 1) void attn_kernel()
{
    extern __shared__ float sm[];
    float* Qs = sm;                 // [o][q], pad 129
    float* KP = sm + 128 * 129;     // Ks: [o][k] pad 132  /  Pt: [k][q] pad 129
    float* Vs = KP + 128 * 132;     // [k][o], pad 132

    const int b  = blockIdx.y;
    const int q0 = blockIdx.x * 128;
    const float* Q = d_theta + (size_t)b * N_ * O_;
    const float* K = d_phi   + (size_t)b * N_ * O_;
    const float* V = d_gv    + (size_t)b * N_ * O_;

    const int tid = threadIdx.x;
    const int tx = tid & 15;   // k / o direction
    const int ty = tid >> 4;   // q direction

    // Load Q tile transposed: Qs[o][q]
#pragma unroll
    for (int r = 0; r < 16; r++) {
        int idx = tid + r * 256;
        int q  = idx >> 5;
        int kv = (idx & 31) << 2;
        float4 v = *(const float4*)(Q + (size_t)(q0 + q) * O_ + kv);
        Qs[(kv + 0) * 129 + q] = v.x;
        Qs[(kv + 1) * 129 + q] = v.y;
        Qs[(kv + 2) * 129 + q] = v.z;
        Qs[(kv + 3) * 129 + q] = v.w;
    }

    float acc[8][8];
    float p[8][8];
    float m[8], l[8];
#pragma unroll
    for (int i = 0; i < 8; i++) {
        m[i] = -1e30f;
        l[i] = 0.f;
#pragma unroll
        for (int j = 0; j < 8; j++) acc[i][j] = 0.f;
    }

    for (int jt = 0; jt < 32; jt++) {
        const int k0 = jt * 128;
        __syncthreads();   // previous PV done (also covers Q-load on first iter)

        // K tile transposed: Ks[o][k].  Lanes along k -> conflict-free STS,
        // strided LDG (L1 absorbs it).
#pragma unroll
        for (int r = 0; r < 16; r++) {
            int idx = tid + r * 256;
            int kq  = idx & 31;
            int grp = idx >> 5;
            int kv  = (grp & 31) << 2;
            int kb  = grp >> 5;
            int k   = kb * 32 + kq;
            float4 v = *(const float4*)(K + (size_t)(k0 + k) * O_ + kv);
            KP[(kv + 0) * 132 + k] = v.x;
            KP[(kv + 1) * 132 + k] = v.y;
            KP[(kv + 2) * 132 + k] = v.z;
            KP[(kv + 3) * 132 + k] = v.w;
        }
        // V tile natural: Vs[k][o], fully coalesced both sides
#pragma unroll
        for (int r = 0; r < 16; r++) {
            int idx = tid + r * 256;
            int k  = idx >> 5;
            int ov = (idx & 31) << 2;
            float4 v = *(const float4*)(V + (size_t)(k0 + k) * O_ + ov);
            *(float4*)&Vs[k * 132 + ov] = v;
        }
        __syncthreads();

        // S = Q K^T  (p holds logits)
#pragma unroll
        for (int i = 0; i < 8; i++)
#pragma unroll
            for (int j = 0; j < 8; j++) p[i][j] = 0.f;
#pragma unroll 4
        for (int kk = 0; kk < 128; kk++) {
            float a[8];
#pragma unroll
            for (int i = 0; i < 8; i++) a[i] = Qs[kk * 129 + ty * 8 + i];
            float4 u = *(const float4*)&KP[kk * 132 + tx * 8];
            float4 v = *(const float4*)&KP[kk * 132 + tx * 8 + 4];
            float bb[8] = {u.x, u.y, u.z, u.w, v.x, v.y, v.z, v.w};
#pragma unroll
            for (int i = 0; i < 8; i++)
#pragma unroll
                for (int j = 0; j < 8; j++) p[i][j] += a[i] * bb[j];
        }

        // Online softmax update (row stats shared across the 16 tx lanes)
#pragma unroll
        for (int i = 0; i < 8; i++) {
            float rm = p[i][0];
#pragma unroll
            for (int j = 1; j < 8; j++) rm = fmaxf(rm, p[i][j]);
            rm = fmaxf(rm, __shfl_xor_sync(0xffffffffu, rm, 8));
            rm = fmaxf(rm, __shfl_xor_sync(0xffffffffu, rm, 4));
            rm = fmaxf(rm, __shfl_xor_sync(0xffffffffu, rm, 2));
            rm = fmaxf(rm, __shfl_xor_sync(0xffffffffu, rm, 1));
            float mn = fmaxf(m[i], rm);
            float sc = __expf(m[i] - mn);
            m[i] = mn;
            float rs = 0.f;
#pragma unroll
            for (int j = 0; j < 8; j++) {
                p[i][j] = __expf(p[i][j] - mn);
                rs += p[i][j];
            }
            rs += __shfl_xor_sync(0xffffffffu, rs, 8);
            rs += __shfl_xor_sync(0xffffffffu, rs, 4);
            rs += __shfl_xor_sync(0xffffffffu, rs, 2);
            rs += __shfl_xor_sync(0xffffffffu, rs, 1);
            l[i] = l[i] * sc + rs;
#pragma unroll
            for (int j = 0; j < 8; j++) acc[i][j] *= sc;
        }

        __syncthreads();   // all lanes done reading Ks
        // Write P transposed: Pt[k][q] (reuses Ks region)
#pragma unroll
        for (int i = 0; i < 8; i++)
#pragma unroll
            for (int j = 0; j < 8; j++)
                KP[(tx * 8 + j) * 129 + ty * 8 + i] = p[i][j];
        __syncthreads();

        // acc += P V
#pragma unroll 4
        for (int kk = 0; kk < 128; kk++) {
            float a[8];
#pragma unroll
            for (int i = 0; i < 8; i++) a[i] = KP[kk * 129 + ty * 8 + i];
            float4 u = *(const float4*)&Vs[kk * 132 + tx * 8];
            float4 v = *(const float4*)&Vs[kk * 132 + tx * 8 + 4];
            float bb[8] = {u.x, u.y, u.z, u.w, v.x, v.y, v.z, v.w};
#pragma unroll
            for (int i = 0; i < 8; i++)
#pragma unroll
                for (int j = 0; j < 8; j++) acc[i][j] += a[i] * bb[j];
        }
    }

    float* Y = d_y + (size_t)b * N_ * O_;
#pragma unroll
    for (int i = 0; i < 8; i++) {
        float inv = 1.f / l[i];
        float* row = Y + (size_t)(q0 + ty * 8 + i) * O_ + tx * 8;
        float4 o0 = make_float4(acc[i][0] * inv, acc[i][1] * inv,
                                acc[i][2] * inv, acc[i][3] * inv);
        float4 o1 = make_float4(acc[i][4] * inv, acc[i][5] * inv,
                                acc[i][6] * inv, acc[i][7] * inv);
        *(float4*)row = o0;
        *(float4*)(row + 4) = o1;
    }
}

// ---------------------------------------------------------------------------
// Kernel 3: out = x + BN(W_out y + b_out).  grid (32 n-tiles, 2 c-tiles, 8 b).
// Tile 128c x 128n, K = O = 128 (single chunk).
// ---------------------------------------------------------------------------
#define OUT_SMEM (2 * 128 * 132 * 4)

__global__ __launch_bounds__(256, 1) void out_kernel(
    const float* __restrict__ x,
    const float* __restrict__ wo, const float* __restrict__ bo,
    const float* __restrict__ gamma, const float* __restrict__ beta,
    const float* __restrict__ mean, const float* __restrict__ var,
    float* __restrict__ out)
{
    extern __shared__ float sm[];
    float* ws2 = sm;              // [o][c], pad 132
    float* ys  = sm + 128 * 132;  // [o][n], pad 132

    const int b  = blockIdx.z;
    const int c0 = blockIdx.y * 128;
    const int n0 = blockIdx.x * 128;
    const int tid = threadIdx.x;
    const int tx = tid & 15;   // n direction
    const int ty = tid >> 4;   // c direction

    // w_out[c][o] -> ws2[o][c]  (lanes along c: conflict-free STS)
#pragma unroll
    for (int r = 0; r < 16; r++) {
        int idx = tid + r * 256;
        int cq  = idx & 31;
        int grp = idx >> 5;
        int ov  = (grp & 31) << 2;
        int cb  = grp >> 5;
        int c   = cb * 32 + cq;
        float4 v = *(const float4*)(wo + (size_t)(c0 + c) * O_ + ov);
        ws2[(ov + 0) * 132 + c] = v.x;
        ws2[(ov + 1) * 132 + c] = v.y;
        ws2[(ov + 2) * 132 + c] = v.z;
        ws2[(ov + 3) * 132 + c] = v.w;
    }
    // y[n][o] -> ys[o][n]  (lanes along n)
#pragma unroll
    for (int r = 0; r < 16; r++) {
        int idx = tid + r * 256;
        int nq  = idx & 31;
        int grp = idx >> 5;
        int ov  = (grp & 31) << 2;
        int nb  = grp >> 5;
        int n   = nb * 32 + nq;
        float4 v = *(const float4*)(d_y + ((size_t)b * N_ + n0 + n) * O_ + ov);
        ys[(ov + 0) * 132 + n] = v.x;
        ys[(ov + 1) * 132 + n] = v.y;
        ys[(ov + 2) * 132 + n] = v.z;
        ys[(ov + 3) * 132 + n] = v.w;
    }
    __syncthreads();

    float acc[8][8];
#pragma unroll
    for (int i = 0; i < 8; i++)
#pragma unroll
        for (int j = 0; j < 8; j++) acc[i][j] = 0.f;

#pragma unroll 4
    for (int o = 0; o < 128; o++) {
        float a[8];
#pragma unroll
        for (int i = 0; i < 8; i++) a[i] = ws2[o * 132 + ty * 8 + i];
        float4 u = *(const float4*)&ys[o * 132 + tx * 8];
        float4 v = *(const float4*)&ys[o * 132 + tx * 8 + 4];
        float bb[8] = {u.x, u.y, u.z, u.w, v.x, v.y, v.z, v.w};
#pragma unroll
        for (int i = 0; i < 8; i++)
#pragma unroll
            for (int j = 0; j < 8; j++) acc[i][j] += a[i] * bb[j];
    }

    // Epilogue: BN (eval) + residual
#pragma unroll
    for (int i = 0; i < 8; i++) {
        int c = c0 + ty * 8 + i;
        float inv = gamma[c] * rsqrtf(var[c] + 1e-5f);
        float sh  = beta[c] - mean[c] * inv + bo[c] * inv;
        const float* xr = x   + ((size_t)(b * C_ + c)) * N_ + n0 + tx * 8;
        float*       orow = out + ((size_t)(b * C_ + c)) * N_ + n0 + tx * 8;
        float4 x0 = *(const float4*)xr;
        float4 x1 = *(const float4*)(xr + 4);
        float4 o0 = make_float4(x0.x + acc[i][0] * inv + sh,
                                x0.y + acc[i][1] * inv + sh,
                                x0.z + acc[i][2] * inv + sh,
                                x0.w + acc[i][3] * inv + sh);
        float4 o1 = make_float4(x1.x + acc[i][4] * inv + sh,
                                x1.y + acc[i][5] * inv + sh,
                                x1.z + acc[i][6] * inv + sh,
                                x1.w + acc[i][7] * inv + sh);
        *(float4*)orow       = o0;
        *(float4*)(orow + 4) = o1;
    }
}

// ---------------------------------------------------------------------------
extern "C" void kernel_launch(void* const* d_in, const int* in_sizes, int n_in,
                              void* d_out, int out_size)
{
    const float* x     = (const float*)d_in[0];
    const float* wt    = (const float*)d_in[1];
    const float* bt    = (const float*)d_in[2];
    const float* wp    = (const float*)d_in[3];
    const float* bp    = (const float*)d_in[4];
    const float* wg    = (const float*)d_in[5];
    const float* bg    = (const float*)d_in[6];
    const float* wo    = (const float*)d_in[7];
    const float* bo    = (const float*)d_in[8];
    const float* gamma = (const float*)d_in[9];
    const float* beta  = (const float*)d_in[10];
    const float* mean  = (const float*)d_in[11];
    const float* var   = (const float*)d_in[12];
    float* out = (float*)d_out;

    cudaFuncSetAttribute(attn_kernel, cudaFuncAttributeMaxDynamicSharedMemorySize, ATTN_SMEM);
    cudaFuncSetAttribute(out_kernel,  cudaFuncAttributeMaxDynamicSharedMemorySize, OUT_SMEM);

    proj_kernel<<<dim3(32, 8, 3), 256>>>(x, wt, bt, wp, bp, wg, bg);
    attn_kernel<<<dim3(32, 8), 256, ATTN_SMEM>>>();
    out_kernel<<<dim3(32, 2, 8), 256, OUT_SMEM>>>(x, wo, bo, gamma, beta, mean, var, out);
}